// round 11
// baseline (speedup 1.0000x reference)
#include <cuda_runtime.h>

#define NBANDS 31
#define NB     16
#define NT     1000
#define NF     257
#define NO     128
#define MAXC   34
#define KTOT   536      // sum of roundup4(2*bw)
#define TT2    16       // time supertile per block
#define NCH    16       // stats chunks per (b,band)
#define OUTW   (NO * NBANDS)   // 3968
#define OQW    (32 * NBANDS)   // 992 floats per (t, o-quarter)

__constant__ int c_bw[NBANDS] = {
    2,3,3,3,3,3,3,3,3,3,3,
    8,8,8,8,8,8,8,8,8,8,8,8,
    16,16,16,16,16,16,16,17
};
__constant__ int c_kal[NBANDS] = {
    0,4,12,20,28,36,44,52,60,68,76,
    84,100,116,132,148,164,180,196,212,228,244,260,
    276,308,340,372,404,436,468,500
};
__constant__ int c_f0[NBANDS] = {
    0,2,5,8,11,14,17,20,23,26,29,
    32,40,48,56,64,72,80,88,96,104,112,120,
    128,144,160,176,192,208,224,240
};
// 16 band-groups (one warp each); padded-C sums 32..44
__constant__ int c_gs[17] = {0,1,2,3,4,5,6,7,8,10,12,14,16,18,21,26,31};
__constant__ int c_gb[31] = {
    30,
    23,24,25,26,27,28,29,
    11,12, 13,14, 15,16, 17,18, 19,20,
    21,22,0,
    1,2,3,4,5,
    6,7,8,9,10
};
// k-slots that are zero-padding
__constant__ int c_pad[22] = {
    10,11,18,19,26,27,34,35,42,43,50,51,58,59,66,67,74,75,82,83,534,535
};

// static scratch
__device__ float  d_A2[NB * KTOT];
__device__ float  d_B2[NB * KTOT];
// per-quarter weights: [qt][kslot][32], pos l holds o = qt*32 + l
__device__ float  d_w2q[4 * KTOT * 32];
__device__ float2 d_ps[NB * NBANDS * NCH];    // partial (sum, sumsq)

__device__ __forceinline__ int kg_of_f(int f)
{
    if (f >= 32) return 2 * f + 20;
    if (f >= 2)  return 2 * f - 2 + 2 * ((f + 1) / 3);
    return 2 * f;
}

__device__ __forceinline__ float2 u2f(unsigned long long u)
{
    float2 r;
    asm("mov.b64 {%0,%1}, %2;" : "=f"(r.x), "=f"(r.y) : "l"(u));
    return r;
}
__device__ __forceinline__ unsigned long long dupf(float f)
{
    unsigned long long r;
    asm("mov.b64 %0, {%1, %1};" : "=l"(r) : "f"(f));
    return r;
}

// ---------------------------------------------------------------------------
// Stats stage 1: partial sums over a t-chunk of x[b, f0:f0+bw, :, :]
// ---------------------------------------------------------------------------
__global__ __launch_bounds__(256)
void stats1(const float* __restrict__ x)
{
    const int b    = blockIdx.x;
    const int band = blockIdx.y;
    const int ch   = blockIdx.z;
    const int bw   = c_bw[band];
    const float4* p = (const float4*)(x + (size_t)(b * NF + c_f0[band]) * (NT * 2));
    const int nv = bw * NT / 2;
    const int i0 = (int)((long long)nv * ch / NCH);
    const int i1 = (int)((long long)nv * (ch + 1) / NCH);

    float4 a1 = make_float4(0.f, 0.f, 0.f, 0.f);
    float4 a2 = a1;
    for (int i = i0 + threadIdx.x; i < i1; i += 256) {
        float4 v = p[i];
        a1.x += v.x; a1.y += v.y; a1.z += v.z; a1.w += v.w;
        a2.x = fmaf(v.x, v.x, a2.x); a2.y = fmaf(v.y, v.y, a2.y);
        a2.z = fmaf(v.z, v.z, a2.z); a2.w = fmaf(v.w, v.w, a2.w);
    }
    float s  = (a1.x + a1.y) + (a1.z + a1.w);
    float s2 = (a2.x + a2.y) + (a2.z + a2.w);
    for (int off = 16; off; off >>= 1) {
        s  += __shfl_down_sync(0xFFFFFFFFu, s,  off);
        s2 += __shfl_down_sync(0xFFFFFFFFu, s2, off);
    }
    __shared__ float sh0[8], sh1[8];
    const int w = threadIdx.x >> 5, l = threadIdx.x & 31;
    if (l == 0) { sh0[w] = s; sh1[w] = s2; }
    __syncthreads();
    if (threadIdx.x == 0) {
        float ts = 0.f, ts2 = 0.f;
        #pragma unroll
        for (int i = 0; i < 8; i++) { ts += sh0[i]; ts2 += sh1[i]; }
        d_ps[(b * NBANDS + band) * NCH + ch] = make_float2(ts, ts2);
    }
}

// ---------------------------------------------------------------------------
// Stage 2 merged: y < NB -> stats finalize; y == NB -> weight transpose prep.
// ---------------------------------------------------------------------------
__global__ __launch_bounds__(256)
void stats2_prep(const float* __restrict__ gnw, const float* __restrict__ gnb,
                 const float* __restrict__ fcw)
{
    const int band = blockIdx.x;
    const int bw   = c_bw[band];
    const int kal  = c_kal[band];

    if (blockIdx.y < NB) {
        const int b = blockIdx.y;
        const int n = bw * NT * 2;
        __shared__ float sh_mean, sh_inv;
        if (threadIdx.x == 0) {
            double ts = 0.0, ts2 = 0.0;
            #pragma unroll
            for (int i = 0; i < NCH; i++) {
                float2 v = d_ps[(b * NBANDS + band) * NCH + i];
                ts += (double)v.x; ts2 += (double)v.y;
            }
            double mean = ts / n;
            double var  = ts2 / n - mean * mean;
            sh_mean = (float)mean;
            sh_inv  = rsqrtf((float)var + 1e-5f);
        }
        __syncthreads();
        const int c = 2 * bw;
        if (threadIdx.x < c) {
            float gw = gnw[band * MAXC + threadIdx.x];
            float gb = gnb[band * MAXC + threadIdx.x];
            float A  = gw * sh_inv;
            d_A2[b * KTOT + kal + threadIdx.x] = A;
            d_B2[b * KTOT + kal + threadIdx.x] = gb - A * sh_mean;
        }
    } else {
        // per-quarter weight prep: d_w2q[qt][kal+k][l] = fcw[band][qt*32+l][k]
        const int C  = 2 * bw;
        const int kp = (C + 3) & ~3;
        for (int idx = threadIdx.x; idx < kp * NO; idx += 256) {
            const int k = idx >> 7;
            const int p = idx & 127;       // p = o
            const int qt = p >> 5;
            const int l  = p & 31;
            d_w2q[((qt * KTOT) + kal + k) * 32 + l] =
                (k < C) ? fcw[(band * NO + p) * MAXC + k] : 0.0f;
        }
    }
}

// ---------------------------------------------------------------------------
// Fused kernel: block = (16-t supertile, batch, o-quarter). Per lane: one o,
// 8 t-pair f32x2 accumulators; weights LDG.32 (4B serves 16 outputs);
// y as [k][16t] read via broadcast LDS.128. Depth-4 weight pipeline.
// All 16 t staged conflict-free, then 16 contiguous bulk stores.
// ---------------------------------------------------------------------------
#define SOUT_F   (TT2 * OQW)                  // 15872 floats (63488 B)
#define SY_F     (KTOT * TT2)                 // 8576 floats  [k][t]
#define SMEM_F   (SOUT_F + SY_F + 2 * KTOT)   // 25520 floats = 102080 B

#define FMA2(acc, wv, yv) \
    asm("fma.rn.f32x2 %0, %1, %2, %0;" : "+l"(acc) : "l"(wv), "l"(yv));

__global__ __launch_bounds__(512, 2)
void fused_kernel(const float* __restrict__ x,
                  const float* __restrict__ fcb,
                  float* __restrict__ out)
{
    extern __shared__ float sm[];
    float* s_out = sm;                        // [t][OQW] exact output order
    float* s_y   = sm + SOUT_F;               // [k][16]
    float* s_A   = sm + SOUT_F + SY_F;
    float* s_B   = s_A + KTOT;

    const int b    = blockIdx.y;
    const int t0   = blockIdx.x * TT2;
    const int qt   = blockIdx.z;              // o-quarter
    const int tid  = threadIdx.x;
    const int lane = tid & 31;
    const int warp = tid >> 5;                // band group

    const float* wbase = d_w2q + (size_t)qt * KTOT * 32 + lane;

    // --- prefetch first band's bias + first 4 weight rows (hidden by y-build)
    int bi          = c_gs[warp];
    const int biEnd = c_gs[warp + 1];
    int band = c_gb[bi];
    int kal  = c_kal[band];
    const float* wp = wbase + kal * 32;
    float bzf = __ldg(fcb + band * NO + qt * 32 + lane);
    float wq0 = __ldg(wp);
    float wq1 = __ldg(wp + 32);
    float wq2 = __ldg(wp + 64);
    float wq3 = __ldg(wp + 96);

    for (int i = tid; i < KTOT; i += 512) {
        s_A[i] = d_A2[b * KTOT + i];
        s_B[i] = d_B2[b * KTOT + i];
    }
    // zero the 22 padded k-slots (16 t's each)
    if (tid < 88) {
        const int slot = c_pad[tid >> 2];
        *(float4*)&s_y[slot * TT2 + (tid & 3) * 4] = make_float4(0.f, 0.f, 0.f, 0.f);
    }
    __syncthreads();

    // y-build: s_y[kg][t] = A*x + B; float4 covers (t,t+1)x(re,im)
    for (int idx = tid; idx < NF * 8; idx += 512) {
        const int f = idx >> 3;
        const int qq = idx & 7;               // t-pair: t = t0+2qq, t0+2qq+1
        float4 v = make_float4(0.f, 0.f, 0.f, 0.f);
        if (t0 + 2 * qq < NT)
            v = *(const float4*)(x + ((size_t)(b * NF + f) * NT + t0) * 2 + qq * 4);
        const int kg = kg_of_f(f);
        const float A0 = s_A[kg], B0 = s_B[kg];
        const float A1 = s_A[kg + 1], B1 = s_B[kg + 1];
        *(float2*)&s_y[kg * TT2 + 2 * qq] =
            make_float2(fmaf(A0, v.x, B0), fmaf(A0, v.z, B0));
        *(float2*)&s_y[(kg + 1) * TT2 + 2 * qq] =
            make_float2(fmaf(A1, v.y, B1), fmaf(A1, v.w, B1));
    }
    __syncthreads();

    // --- band loop, depth-4 pipelined weight stream (one float per lane/row)
    for (;;) {
        const int kcnt = (2 * c_bw[band] + 3) & ~3;
        const float* yb = s_y + kal * TT2;

        unsigned long long acc[8];    // 8 t-pairs, one o
        {
            const unsigned long long bd = dupf(bzf);
            #pragma unroll
            for (int tp = 0; tp < 8; tp++) acc[tp] = bd;
        }

        #pragma unroll 4
        for (int k = 0; k < kcnt; k++) {
            const float w = wq0;
            wq0 = wq1; wq1 = wq2; wq2 = wq3;
            const int kn = (k + 4 < kcnt) ? k + 4 : k;   // clamp (L1 hit on reload)
            wq3 = __ldg(wp + kn * 32);

            const unsigned long long wA = dupf(w);
            #pragma unroll
            for (int tpp = 0; tpp < 4; tpp++) {
                const ulonglong2 y2 =
                    *(const ulonglong2*)(yb + k * TT2 + 4 * tpp);  // broadcast LDS.128
                FMA2(acc[2 * tpp    ], wA, y2.x)
                FMA2(acc[2 * tpp + 1], wA, y2.y)
            }
        }

        // prefetch next band before staging stores
        const int curBand = band;
        const bool more = (++bi < biEnd);
        if (more) {
            band = c_gb[bi];
            kal  = c_kal[band];
            wp   = wbase + kal * 32;
            bzf  = __ldg(fcb + band * NO + qt * 32 + lane);
            wq0 = __ldg(wp); wq1 = __ldg(wp + 32);
            wq2 = __ldg(wp + 64); wq3 = __ldg(wp + 96);
        }

        // conflict-free staging: addr = t*OQW + 31*lane + band; OQW ≡ 0 mod 32
        #pragma unroll
        for (int tp = 0; tp < 8; tp++) {
            float* so = s_out + (2 * tp) * OQW + 31 * lane + curBand;
            float2 pa = u2f(acc[tp]);       // t = 2tp, 2tp+1
            so[0]   = pa.x;
            so[OQW] = pa.y;
        }
        if (!more) break;
    }
    __syncthreads();

    // 16 contiguous bulk stores of 3968 B each (o-quarter slab per t)
    if (tid == 0) {
        unsigned int saddr;
        asm("{ .reg .u64 t; cvta.to.shared.u64 t, %1; cvt.u32.u64 %0, t; }"
            : "=r"(saddr) : "l"(s_out));
        asm volatile("fence.proxy.async.shared::cta;" ::: "memory");
        #pragma unroll
        for (int t = 0; t < TT2; t++) {
            if (t0 + t < NT) {
                float* dst = out + (size_t)(b * NT + t0 + t) * OUTW + qt * OQW;
                asm volatile("cp.async.bulk.global.shared::cta.bulk_group [%0], [%1], %2;"
                             :: "l"(dst), "r"(saddr + t * (OQW * 4)), "n"(OQW * 4)
                             : "memory");
            }
        }
        asm volatile("cp.async.bulk.commit_group;" ::: "memory");
        asm volatile("cp.async.bulk.wait_group.read 0;" ::: "memory");
    }
}

// ---------------------------------------------------------------------------
extern "C" void kernel_launch(void* const* d_in, const int* in_sizes, int n_in,
                              void* d_out, int out_size)
{
    const float* x   = (const float*)d_in[0];
    const float* gnw = (const float*)d_in[1];
    const float* gnb = (const float*)d_in[2];
    const float* fcw = (const float*)d_in[3];
    const float* fcb = (const float*)d_in[4];
    float* out = (float*)d_out;

    const int smem_bytes = SMEM_F * 4;
    cudaFuncSetAttribute(fused_kernel,
                         cudaFuncAttributeMaxDynamicSharedMemorySize, smem_bytes);

    stats1<<<dim3(NB, NBANDS, NCH), 256>>>(x);
    stats2_prep<<<dim3(NBANDS, NB + 1), 256>>>(gnw, gnb, fcw);
    fused_kernel<<<dim3((NT + TT2 - 1) / TT2, NB, 4), 512, smem_bytes>>>(x, fcb, out);
}

// round 12
// speedup vs baseline: 1.3113x; 1.3113x over previous
#include <cuda_runtime.h>

#define NBANDS 31
#define NB     16
#define NT     1000
#define NF     257
#define NO     128
#define MAXC   34
#define KTOT   536      // sum of roundup4(2*bw)
#define TT     8        // time tile per block
#define NCH    8        // stats chunks per (b,band)
#define OUTW   (NO * NBANDS)   // 3968
#define OHW    (64 * NBANDS)   // 1984 floats per (t, o-half)

__constant__ int c_bw[NBANDS] = {
    2,3,3,3,3,3,3,3,3,3,3,
    8,8,8,8,8,8,8,8,8,8,8,8,
    16,16,16,16,16,16,16,17
};
__constant__ int c_kal[NBANDS] = {
    0,4,12,20,28,36,44,52,60,68,76,
    84,100,116,132,148,164,180,196,212,228,244,260,
    276,308,340,372,404,436,468,500
};
__constant__ int c_f0[NBANDS] = {
    0,2,5,8,11,14,17,20,23,26,29,
    32,40,48,56,64,72,80,88,96,104,112,120,
    128,144,160,176,192,208,224,240
};
// 16 band-groups (one warp each); padded-C sums 32..44
__constant__ int c_gs[17] = {0,1,2,3,4,5,6,7,8,10,12,14,16,18,21,26,31};
__constant__ int c_gb[31] = {
    30,
    23,24,25,26,27,28,29,
    11,12, 13,14, 15,16, 17,18, 19,20,
    21,22,0,
    1,2,3,4,5,
    6,7,8,9,10
};
// k-slots that are zero-padding
__constant__ int c_pad[22] = {
    10,11,18,19,26,27,34,35,42,43,50,51,58,59,66,67,74,75,82,83,534,535
};

// static scratch
__device__ float  d_A2[NB * KTOT];
__device__ float  d_B2[NB * KTOT];
// per-half weights: [h][kslot][64], pos 2l+s holds o = h*64 + l + 32*s
__device__ float  d_w2h[2 * KTOT * 64];
// bias, same per-half pairing: [band][h][64]
__device__ float  d_bp[NBANDS * NO];
__device__ float2 d_ps[NB * NBANDS * NCH];    // partial (sum, sumsq)

__device__ __forceinline__ int kg_of_f(int f)
{
    if (f >= 32) return 2 * f + 20;
    if (f >= 2)  return 2 * f - 2 + 2 * ((f + 1) / 3);
    return 2 * f;
}

__device__ __forceinline__ float2 u2f(unsigned long long u)
{
    float2 r;
    asm("mov.b64 {%0,%1}, %2;" : "=f"(r.x), "=f"(r.y) : "l"(u));
    return r;
}
__device__ __forceinline__ unsigned long long dupf(float f)
{
    unsigned long long r;
    asm("mov.b64 %0, {%1, %1};" : "=l"(r) : "f"(f));
    return r;
}

// ---------------------------------------------------------------------------
// Stats stage 1: partial sums over a t-chunk of x[b, f0:f0+bw, :, :]
// ---------------------------------------------------------------------------
__global__ __launch_bounds__(256)
void stats1(const float* __restrict__ x)
{
    const int b    = blockIdx.x;
    const int band = blockIdx.y;
    const int ch   = blockIdx.z;
    const int bw   = c_bw[band];
    const float4* p = (const float4*)(x + (size_t)(b * NF + c_f0[band]) * (NT * 2));
    const int nv = bw * NT / 2;
    const int i0 = (int)((long long)nv * ch / NCH);
    const int i1 = (int)((long long)nv * (ch + 1) / NCH);

    float4 a1 = make_float4(0.f, 0.f, 0.f, 0.f);
    float4 a2 = a1;
    for (int i = i0 + threadIdx.x; i < i1; i += 256) {
        float4 v = p[i];
        a1.x += v.x; a1.y += v.y; a1.z += v.z; a1.w += v.w;
        a2.x = fmaf(v.x, v.x, a2.x); a2.y = fmaf(v.y, v.y, a2.y);
        a2.z = fmaf(v.z, v.z, a2.z); a2.w = fmaf(v.w, v.w, a2.w);
    }
    float s  = (a1.x + a1.y) + (a1.z + a1.w);
    float s2 = (a2.x + a2.y) + (a2.z + a2.w);
    for (int off = 16; off; off >>= 1) {
        s  += __shfl_down_sync(0xFFFFFFFFu, s,  off);
        s2 += __shfl_down_sync(0xFFFFFFFFu, s2, off);
    }
    __shared__ float sh0[8], sh1[8];
    const int w = threadIdx.x >> 5, l = threadIdx.x & 31;
    if (l == 0) { sh0[w] = s; sh1[w] = s2; }
    __syncthreads();
    if (threadIdx.x == 0) {
        float ts = 0.f, ts2 = 0.f;
        #pragma unroll
        for (int i = 0; i < 8; i++) { ts += sh0[i]; ts2 += sh1[i]; }
        d_ps[(b * NBANDS + band) * NCH + ch] = make_float2(ts, ts2);
    }
}

// ---------------------------------------------------------------------------
// Stage 2 merged: y < NB -> stats finalize; y == NB -> weight/bias prep.
// ---------------------------------------------------------------------------
__global__ __launch_bounds__(256)
void stats2_prep(const float* __restrict__ gnw, const float* __restrict__ gnb,
                 const float* __restrict__ fcw, const float* __restrict__ fcb)
{
    const int band = blockIdx.x;
    const int bw   = c_bw[band];
    const int kal  = c_kal[band];

    if (blockIdx.y < NB) {
        const int b = blockIdx.y;
        const int n = bw * NT * 2;
        __shared__ float sh_mean, sh_inv;
        if (threadIdx.x == 0) {
            double ts = 0.0, ts2 = 0.0;
            #pragma unroll
            for (int i = 0; i < NCH; i++) {
                float2 v = d_ps[(b * NBANDS + band) * NCH + i];
                ts += (double)v.x; ts2 += (double)v.y;
            }
            double mean = ts / n;
            double var  = ts2 / n - mean * mean;
            sh_mean = (float)mean;
            sh_inv  = rsqrtf((float)var + 1e-5f);
        }
        __syncthreads();
        const int c = 2 * bw;
        if (threadIdx.x < c) {
            float gw = gnw[band * MAXC + threadIdx.x];
            float gb = gnb[band * MAXC + threadIdx.x];
            float A  = gw * sh_inv;
            d_A2[b * KTOT + kal + threadIdx.x] = A;
            d_B2[b * KTOT + kal + threadIdx.x] = gb - A * sh_mean;
        }
    } else {
        // per-half weight prep: d_w2h[h][kal+k][2l+s] = w[o = h*64+l+32s]
        const int C  = 2 * bw;
        const int kp = (C + 3) & ~3;
        for (int idx = threadIdx.x; idx < kp * NO; idx += 256) {
            const int k = idx >> 7;
            const int p = idx & 127;
            const int h = p >> 6;
            const int r = p & 63;
            const int l = r >> 1;
            const int s = r & 1;
            const int o = h * 64 + l + 32 * s;
            d_w2h[(h * KTOT + kal + k) * 64 + 2 * l + s] =
                (k < C) ? fcw[(band * NO + o) * MAXC + k] : 0.0f;
        }
        if (threadIdx.x < NO) {
            const int p = threadIdx.x;
            const int h = p >> 6;
            const int r = p & 63;
            const int l = r >> 1;
            const int s = r & 1;
            d_bp[band * NO + p] = fcb[band * NO + h * 64 + l + 32 * s];
        }
    }
}

// ---------------------------------------------------------------------------
// Fused kernel: block = (t-tile of 8, batch, o-half). t-pair f32x2 packing:
// acc = {out[t],out[t+1]}, y natural [k][8t] read via 2x LDS.128 broadcast,
// weights dup'd in-register. Depth-4 weight pipeline. Contiguous bulk stores.
// ---------------------------------------------------------------------------
#define SOUT_F   (TT * OHW)                   // 15872 floats (63488 B)
#define SY_F     (KTOT * TT)                  // 4288 floats  [k][t]
#define SMEM_F   (SOUT_F + SY_F + 2 * KTOT)   // 21232 floats = 84928 B

#define FMA2(acc, wv, yv) \
    asm("fma.rn.f32x2 %0, %1, %2, %0;" : "+l"(acc) : "l"(wv), "l"(yv));

__global__ __launch_bounds__(512, 2)
void fused_kernel(const float* __restrict__ x,
                  float* __restrict__ out)
{
    extern __shared__ float sm[];
    float* s_out = sm;                        // [t][OHW] exact output order
    float* s_y   = sm + SOUT_F;               // [k][8]
    float* s_A   = sm + SOUT_F + SY_F;
    float* s_B   = s_A + KTOT;

    const int b    = blockIdx.y;
    const int t0   = blockIdx.x * TT;
    const int h    = blockIdx.z;              // o-half
    const int tid  = threadIdx.x;
    const int lane = tid & 31;
    const int warp = tid >> 5;                // band group

    const unsigned long long* wbase =
        (const unsigned long long*)d_w2h + (size_t)h * KTOT * 32;

    // --- prefetch first band's bias + first 4 weight rows (hidden by y-build)
    int bi          = c_gs[warp];
    const int biEnd = c_gs[warp + 1];
    int band = c_gb[bi];
    int kal  = c_kal[band];
    unsigned long long bz =
        *((const unsigned long long*)(d_bp + band * NO + h * 64) + lane);
    const unsigned long long* wp = wbase + kal * 32 + lane;
    unsigned long long wq0 = wp[0];
    unsigned long long wq1 = wp[32];
    unsigned long long wq2 = wp[64];
    unsigned long long wq3 = wp[96];

    for (int i = tid; i < KTOT; i += 512) {
        s_A[i] = d_A2[b * KTOT + i];
        s_B[i] = d_B2[b * KTOT + i];
    }
    // zero the 22 padded k-slots (all 8 t's each)
    if (tid < 22 * TT) {
        const int slot = c_pad[tid >> 3];
        s_y[slot * TT + (tid & 7)] = 0.0f;
    }
    __syncthreads();

    // y-build: s_y[kg][t] = A*x + B; float4 covers (t,t+1)x(re,im) -> 2 STS.64
    for (int idx = tid; idx < NF * 4; idx += 512) {
        const int f = idx >> 2;
        const int q = idx & 3;                // t-pair q: t = t0+2q, t0+2q+1
        const float4 v = *(const float4*)(x + ((size_t)(b * NF + f) * NT + t0) * 2 + q * 4);
        const int kg = kg_of_f(f);
        const float A0 = s_A[kg], B0 = s_B[kg];
        const float A1 = s_A[kg + 1], B1 = s_B[kg + 1];
        *(float2*)&s_y[kg * TT + 2 * q] =
            make_float2(fmaf(A0, v.x, B0), fmaf(A0, v.z, B0));
        *(float2*)&s_y[(kg + 1) * TT + 2 * q] =
            make_float2(fmaf(A1, v.y, B1), fmaf(A1, v.w, B1));
    }
    __syncthreads();

    // --- band loop, depth-4 pipelined weight stream
    for (;;) {
        const int kcnt = (2 * c_bw[band] + 3) & ~3;
        const float* yb = s_y + kal * TT;

        unsigned long long acc[4][2];   // [t-pair][oA/oB]
        {
            float2 bf = u2f(bz);
            unsigned long long bA = dupf(bf.x), bB = dupf(bf.y);
            #pragma unroll
            for (int tp = 0; tp < 4; tp++) { acc[tp][0] = bA; acc[tp][1] = bB; }
        }

        #pragma unroll 4
        for (int k = 0; k < kcnt; k++) {
            const unsigned long long w = wq0;
            wq0 = wq1; wq1 = wq2; wq2 = wq3;
            const int kn = (k + 4 < kcnt) ? k + 4 : k;   // clamp (L1 hit on reload)
            wq3 = wp[kn * 32];

            float2 wf = u2f(w);
            const unsigned long long wA = dupf(wf.x);
            const unsigned long long wB = dupf(wf.y);

            // whole y row (8 floats, 32B, 16B-aligned): 2x broadcast LDS.128
            const ulonglong2 y01 = *(const ulonglong2*)(yb + k * TT);      // t-pairs 0,1
            const ulonglong2 y23 = *(const ulonglong2*)(yb + k * TT + 4);  // t-pairs 2,3
            FMA2(acc[0][0], wA, y01.x) FMA2(acc[0][1], wB, y01.x)
            FMA2(acc[1][0], wA, y01.y) FMA2(acc[1][1], wB, y01.y)
            FMA2(acc[2][0], wA, y23.x) FMA2(acc[2][1], wB, y23.x)
            FMA2(acc[3][0], wA, y23.y) FMA2(acc[3][1], wB, y23.y)
        }

        // prefetch next band before staging stores
        const int curBand = band;
        const bool more = (++bi < biEnd);
        if (more) {
            band = c_gb[bi];
            kal  = c_kal[band];
            wp   = wbase + kal * 32 + lane;
            bz   = *((const unsigned long long*)(d_bp + band * NO + h * 64) + lane);
            wq0 = wp[0]; wq1 = wp[32]; wq2 = wp[64]; wq3 = wp[96];
        }

        // conflict-free staging: addr = 31*lane + band (+992 for oB), both
        // strides (TT-row 1984, o-offset 992) are 0 mod 32
        #pragma unroll
        for (int tp = 0; tp < 4; tp++) {
            float* so = s_out + (2 * tp) * OHW + 31 * lane + curBand;
            float2 pa = u2f(acc[tp][0]);    // o = h*64 + lane,    t / t+1
            float2 pb = u2f(acc[tp][1]);    // o = h*64 + lane+32
            so[0]         = pa.x;
            so[OHW]       = pa.y;
            so[992]       = pb.x;
            so[OHW + 992] = pb.y;
        }
        if (!more) break;
    }
    __syncthreads();

    // per-t contiguous bulk copies: 7936 B each (o-half slab is contiguous)
    if (tid == 0) {
        unsigned int saddr;
        asm("{ .reg .u64 t; cvta.to.shared.u64 t, %1; cvt.u32.u64 %0, t; }"
            : "=r"(saddr) : "l"(s_out));
        asm volatile("fence.proxy.async.shared::cta;" ::: "memory");
        #pragma unroll
        for (int t = 0; t < TT; t++) {
            float* dst = out + (size_t)(b * NT + t0 + t) * OUTW + h * OHW;
            asm volatile("cp.async.bulk.global.shared::cta.bulk_group [%0], [%1], %2;"
                         :: "l"(dst), "r"(saddr + t * (OHW * 4)), "n"(OHW * 4)
                         : "memory");
        }
        asm volatile("cp.async.bulk.commit_group;" ::: "memory");
        asm volatile("cp.async.bulk.wait_group.read 0;" ::: "memory");
    }
}

// ---------------------------------------------------------------------------
extern "C" void kernel_launch(void* const* d_in, const int* in_sizes, int n_in,
                              void* d_out, int out_size)
{
    const float* x   = (const float*)d_in[0];
    const float* gnw = (const float*)d_in[1];
    const float* gnb = (const float*)d_in[2];
    const float* fcw = (const float*)d_in[3];
    const float* fcb = (const float*)d_in[4];
    float* out = (float*)d_out;

    const int smem_bytes = SMEM_F * 4;
    cudaFuncSetAttribute(fused_kernel,
                         cudaFuncAttributeMaxDynamicSharedMemorySize, smem_bytes);

    stats1<<<dim3(NB, NBANDS, NCH), 256>>>(x);
    stats2_prep<<<dim3(NBANDS, NB + 1), 256>>>(gnw, gnb, fcw, fcb);
    fused_kernel<<<dim3(NT / TT, NB, 2), 512, smem_bytes>>>(x, out);
}